// round 1
// baseline (speedup 1.0000x reference)
#include <cuda_runtime.h>
#include <math.h>

// ---------------- problem constants ----------------
#define S   8
#define T   12
#define H   256
#define F   316
#define B   1024
#define L   48
#define G   1024      // 4*H
#define KVW 512       // packed k|v row width

// ---------------- scratch (device globals; no allocs allowed) ----------------
__device__ float g_Gin[96l * B * G];      // encoder input gates, [s*12+t][b][g]   (~402 MB)
__device__ float g_enc[(long)T * S * B * H];   // encoder outputs [t][s][b][h]      (~100 MB)
__device__ float g_kv [(long)T * S * B * KVW]; // packed K|V [t][s][b][0:256=k,256:512=v] (~201 MB)
__device__ float g_h  [S * B * H];
__device__ float g_c  [S * B * H];
__device__ float g_gates[S * B * G];
__device__ float g_q  [S * B * H];
__device__ float g_ctx[S * B * H];
__device__ float g_ctx2[S * B * H];
__device__ float g_inp[L * B];
__device__ float g_outs[(long)L * S * B];

// ---------------- prep: zero h/c, build teacher-forced decoder inputs ----------------
__global__ void prep_kernel(const float* __restrict__ x, const float* __restrict__ tgt) {
    int i = blockIdx.x * blockDim.x + threadIdx.x;
    if (i < S * B * H) { g_h[i] = 0.f; g_c[i] = 0.f; }
    if (i < L * B) {
        int l = i / B, b = i % B;
        g_inp[i] = (l == 0) ? x[(long)b * 96 * F + 95 * F + 0]
                            : tgt[(long)b * L + (l - 1)];
    }
}

// ---------------- generic batched tiled GEMM ----------------
// C[z][m][n] = sum_k A[z][m][k] * W[wi][n][k]   (both K-major, "NT")
//   wi = (z / wdiv) & 7
// epilogue: + b1[n] + b2[n] + add[z][m][n] + rvec[m]*cvec[n]   (all nullable)
#define BM 64
#define BN 64
#define BK 16
#define SMP 68

__global__ void gemm_k(
    const float* __restrict__ A, long sAz, int lda,
    const float* __restrict__ W, long sWz, int ldw,
    const float* __restrict__ b1, const float* __restrict__ b2, long sBz,
    const float* __restrict__ add, long sAddz, int ldadd,
    const float* __restrict__ rvec, const float* __restrict__ cvec, long sCvz,
    float* __restrict__ C, long sCz, int ldc,
    int K, int wdiv)
{
    __shared__ float As[BK][SMP];
    __shared__ float Ws[BK][SMP];

    int z  = blockIdx.z;
    int wi = (z / wdiv) & 7;

    A += (long)z * sAz + (long)blockIdx.y * BM * lda;
    W += (long)wi * sWz + (long)blockIdx.x * BN * ldw;
    C += (long)z * sCz + (long)blockIdx.y * BM * ldc + blockIdx.x * BN;
    if (b1)   b1   += (long)wi * sBz  + blockIdx.x * BN;
    if (b2)   b2   += (long)wi * sBz  + blockIdx.x * BN;
    if (add)  add  += (long)z * sAddz + (long)blockIdx.y * BM * ldadd + blockIdx.x * BN;
    if (cvec) cvec += (long)wi * sCvz + blockIdx.x * BN;
    if (rvec) rvec += blockIdx.y * BM;

    int t  = threadIdx.x;        // 0..255
    int lr = t >> 2;             // load row 0..63
    int lk = (t & 3) * 4;        // load k-offset {0,4,8,12}
    int tx = t & 15, ty = t >> 4;

    float acc[4][4];
#pragma unroll
    for (int i = 0; i < 4; i++)
#pragma unroll
        for (int j = 0; j < 4; j++) acc[i][j] = 0.f;

    for (int k0 = 0; k0 < K; k0 += BK) {
#pragma unroll
        for (int u = 0; u < 4; u++) {
            int k = k0 + lk + u;
            As[lk + u][lr] = (k < K) ? A[(long)lr * lda + k] : 0.f;
            Ws[lk + u][lr] = (k < K) ? W[(long)lr * ldw + k] : 0.f;
        }
        __syncthreads();
#pragma unroll
        for (int kk = 0; kk < BK; kk++) {
            float4 av = *(const float4*)&As[kk][ty * 4];
            float4 wv = *(const float4*)&Ws[kk][tx * 4];
            float a[4] = {av.x, av.y, av.z, av.w};
            float w[4] = {wv.x, wv.y, wv.z, wv.w};
#pragma unroll
            for (int i = 0; i < 4; i++)
#pragma unroll
                for (int j = 0; j < 4; j++)
                    acc[i][j] = fmaf(a[i], w[j], acc[i][j]);
        }
        __syncthreads();
    }

#pragma unroll
    for (int i = 0; i < 4; i++) {
        int m = ty * 4 + i;
        float rv = rvec ? rvec[m] : 0.f;
#pragma unroll
        for (int j = 0; j < 4; j++) {
            int n = tx * 4 + j;
            float v = acc[i][j];
            if (b1)   v += b1[n];
            if (b2)   v += b2[n];
            if (add)  v += add[(long)m * ldadd + n];
            if (cvec) v += rv * cvec[n];
            C[(long)m * ldc + n] = v;
        }
    }
}

// ---------------- elementwise LSTM cell ----------------
__device__ __forceinline__ float sigf(float x) { return 1.f / (1.f + __expf(-x)); }

__global__ void lstm_kernel(float* __restrict__ encout) {   // encout nullable
    int idx = blockIdx.x * blockDim.x + threadIdx.x;
    if (idx >= S * B * H) return;
    int j  = idx & (H - 1);
    int sb = idx >> 8;                         // s*B + b
    const float* g = g_gates + (long)sb * G;
    float i_ = g[j], f_ = g[H + j], gg = g[2 * H + j], o_ = g[3 * H + j];
    float c = sigf(f_) * g_c[idx] + sigf(i_) * tanhf(gg);
    float h = sigf(o_) * tanhf(c);
    g_c[idx] = c;
    g_h[idx] = h;
    if (encout) encout[idx] = h;
}

// ---------------- single-query attention: one warp per (s,b) ----------------
__global__ void attn_kernel() {
    int gtid = blockIdx.x * blockDim.x + threadIdx.x;
    int warp = gtid >> 5;                // = s*B + b
    int lane = threadIdx.x & 31;
    if (warp >= S * B) return;

    const float* qp = g_q + (long)warp * H;
    float4 q0 = *(const float4*)&qp[lane * 4];
    float4 q1 = *(const float4*)&qp[128 + lane * 4];

    float sc[T];
#pragma unroll
    for (int tt = 0; tt < T; tt++) {
        const float* kp = g_kv + ((long)tt * S * B + warp) * KVW;
        float4 k0 = *(const float4*)&kp[lane * 4];
        float4 k1 = *(const float4*)&kp[128 + lane * 4];
        float d = q0.x * k0.x + q0.y * k0.y + q0.z * k0.z + q0.w * k0.w
                + q1.x * k1.x + q1.y * k1.y + q1.z * k1.z + q1.w * k1.w;
#pragma unroll
        for (int off = 16; off; off >>= 1) d += __shfl_xor_sync(0xffffffffu, d, off);
        sc[tt] = d * 0.0625f;            // 1/sqrt(256)
    }
    float mx = sc[0];
#pragma unroll
    for (int tt = 1; tt < T; tt++) mx = fmaxf(mx, sc[tt]);
    float sum = 0.f;
#pragma unroll
    for (int tt = 0; tt < T; tt++) { sc[tt] = __expf(sc[tt] - mx); sum += sc[tt]; }
    float inv = 1.f / sum;

    float a0=0,a1=0,a2=0,a3=0,b0=0,b1=0,b2=0,b3=0;
#pragma unroll
    for (int tt = 0; tt < T; tt++) {
        float w = sc[tt] * inv;
        const float* vp = g_kv + ((long)tt * S * B + warp) * KVW + H;
        float4 v0 = *(const float4*)&vp[lane * 4];
        float4 v1 = *(const float4*)&vp[128 + lane * 4];
        a0 = fmaf(w, v0.x, a0); a1 = fmaf(w, v0.y, a1);
        a2 = fmaf(w, v0.z, a2); a3 = fmaf(w, v0.w, a3);
        b0 = fmaf(w, v1.x, b0); b1 = fmaf(w, v1.y, b1);
        b2 = fmaf(w, v1.z, b2); b3 = fmaf(w, v1.w, b3);
    }
    float* cp = g_ctx + (long)warp * H;
    *(float4*)&cp[lane * 4]       = make_float4(a0, a1, a2, a3);
    *(float4*)&cp[128 + lane * 4] = make_float4(b0, b1, b2, b3);
}

// ---------------- fcout: outs[l][s][b] = [h,ctx2] . W_fcout[s] + b ----------------
__global__ void fcout_kernel(const float* __restrict__ Wf, const float* __restrict__ bf, int l) {
    int gtid = blockIdx.x * blockDim.x + threadIdx.x;
    int warp = gtid >> 5;                // = s*B + b
    int lane = threadIdx.x & 31;
    if (warp >= S * B) return;
    int s = warp >> 10;

    const float* hp = g_h    + (long)warp * H;
    const float* cp = g_ctx2 + (long)warp * H;
    const float* w  = Wf + (long)s * 2 * H;

    float d = 0.f;
#pragma unroll
    for (int u = 0; u < 2; u++) {
        int e = lane * 4 + u * 128;
        float4 hv  = *(const float4*)&hp[e];
        float4 wv  = *(const float4*)&w[e];
        d += hv.x * wv.x + hv.y * wv.y + hv.z * wv.z + hv.w * wv.w;
        float4 cv  = *(const float4*)&cp[e];
        float4 wv2 = *(const float4*)&w[H + e];
        d += cv.x * wv2.x + cv.y * wv2.y + cv.z * wv2.z + cv.w * wv2.w;
    }
#pragma unroll
    for (int off = 16; off; off >>= 1) d += __shfl_xor_sync(0xffffffffu, d, off);
    if (lane == 0) g_outs[(long)l * S * B + warp] = d + bf[s];
}

// ---------------- final mix: out[b][l] = sum_s outs[l][s][b]*Wfc[s] + bfc ----------------
__global__ void final_kernel(const float* __restrict__ Wfc, const float* __restrict__ bfc,
                             float* __restrict__ out) {
    int i = blockIdx.x * blockDim.x + threadIdx.x;   // i = b*L + l
    if (i >= B * L) return;
    int b = i / L, l = i % L;
    float acc = bfc[0];
#pragma unroll
    for (int s = 0; s < S; s++)
        acc += g_outs[(long)l * S * B + (long)s * B + b] * Wfc[s];
    out[i] = acc;
}

// ---------------- host launch (graph-capturable: kernels only) ----------------
extern "C" void kernel_launch(void* const* d_in, const int* in_sizes, int n_in,
                              void* d_out, int out_size) {
    const float* x       = (const float*)d_in[0];
    const float* tgt     = (const float*)d_in[1];
    const float* W_ih_e  = (const float*)d_in[2];
    const float* W_hh_e  = (const float*)d_in[3];
    const float* b_ih_e  = (const float*)d_in[4];
    const float* b_hh_e  = (const float*)d_in[5];
    const float* W_ih_d  = (const float*)d_in[6];
    const float* W_hh_d  = (const float*)d_in[7];
    const float* b_ih_d  = (const float*)d_in[8];
    const float* b_hh_d  = (const float*)d_in[9];
    const float* W_in    = (const float*)d_in[10];
    const float* b_in    = (const float*)d_in[11];
    const float* W_out   = (const float*)d_in[12];
    const float* b_out   = (const float*)d_in[13];
    const float* W_fcout = (const float*)d_in[14];
    const float* b_fcout = (const float*)d_in[15];
    const float* W_fc    = (const float*)d_in[16];
    const float* b_fc    = (const float*)d_in[17];
    float* out = (float*)d_out;

    float *Gin, *enc, *kv, *hh, *gates, *q, *ctx, *ctx2, *inp;
    cudaGetSymbolAddress((void**)&Gin,   g_Gin);
    cudaGetSymbolAddress((void**)&enc,   g_enc);
    cudaGetSymbolAddress((void**)&kv,    g_kv);
    cudaGetSymbolAddress((void**)&hh,    g_h);
    cudaGetSymbolAddress((void**)&gates, g_gates);
    cudaGetSymbolAddress((void**)&q,     g_q);
    cudaGetSymbolAddress((void**)&ctx,   g_ctx);
    cudaGetSymbolAddress((void**)&ctx2,  g_ctx2);
    cudaGetSymbolAddress((void**)&inp,   g_inp);

    prep_kernel<<<(S * B * H + 255) / 256, 256>>>(x, tgt);

    // 1) All encoder input projections: Gin[z][b][g], z = s*12+t  (biases folded in)
    gemm_k<<<dim3(G / 64, B / 64, 96), 256>>>(
        x, (long)F, 96 * F,
        W_ih_e, (long)G * F, F,
        b_ih_e, b_hh_e, G,
        nullptr, 0, 0,
        nullptr, nullptr, 0,
        Gin, (long)B * G, G, F, 12);

    // 2) Encoder recurrence
    for (int tt = 0; tt < T; tt++) {
        gemm_k<<<dim3(G / 64, B / 64, S), 256>>>(
            hh, (long)B * H, H,
            W_hh_e, (long)G * H, H,
            nullptr, nullptr, 0,
            Gin + (long)tt * B * G, (long)T * B * G, G,
            nullptr, nullptr, 0,
            gates, (long)B * G, G, H, 1);
        lstm_kernel<<<(S * B * H + 255) / 256, 256>>>(enc + (long)tt * S * B * H);
    }

    // 3) K|V packed projection: z = t*S + s
    gemm_k<<<dim3(KVW / 64, B / 64, T * S), 256>>>(
        enc, (long)B * H, H,
        W_in + H * H, (long)3 * H * H, H,       // rows 256..767 = [Wk; Wv]
        b_in + H, nullptr, (long)3 * H,
        nullptr, 0, 0,
        nullptr, nullptr, 0,
        kv, (long)B * KVW, KVW, H, 1);

    // 4) Decoder: 48 teacher-forced steps
    for (int l = 0; l < L; l++) {
        gemm_k<<<dim3(G / 64, B / 64, S), 256>>>(          // LSTM gates (+ rank-1 input)
            hh, (long)B * H, H,
            W_hh_d, (long)G * H, H,
            b_ih_d, b_hh_d, G,
            nullptr, 0, 0,
            inp + (long)l * B, W_ih_d, G,
            gates, (long)B * G, G, H, 1);
        lstm_kernel<<<(S * B * H + 255) / 256, 256>>>(nullptr);
        gemm_k<<<dim3(H / 64, B / 64, S), 256>>>(           // Q projection
            hh, (long)B * H, H,
            W_in, (long)3 * H * H, H,
            b_in, nullptr, (long)3 * H,
            nullptr, 0, 0,
            nullptr, nullptr, 0,
            q, (long)B * H, H, H, 1);
        attn_kernel<<<(S * B * 32 + 255) / 256, 256>>>();
        gemm_k<<<dim3(H / 64, B / 64, S), 256>>>(           // attention out-proj
            ctx, (long)B * H, H,
            W_out, (long)H * H, H,
            b_out, nullptr, (long)H,
            nullptr, 0, 0,
            nullptr, nullptr, 0,
            ctx2, (long)B * H, H, H, 1);
        fcout_kernel<<<(S * B * 32 + 255) / 256, 256>>>(W_fcout, b_fcout, l);
    }

    // 5) Final 8->1 mix
    final_kernel<<<(B * L + 255) / 256, 256>>>(W_fc, b_fc, out);
}

// round 2
// speedup vs baseline: 1.2383x; 1.2383x over previous
#include <cuda_runtime.h>
#include <math.h>

// ---------------- problem constants ----------------
#define S   8
#define T   12
#define H   256
#define F   316
#define B   1024
#define L   48
#define G   1024      // 4*H

// ---------------- scratch (device globals; no allocs allowed) ----------------
__device__ float g_Gin[96l * B * G];           // encoder input gates [s*12+t][b][g]
__device__ float g_enc[(long)T * S * B * H];   // encoder outputs [t][s][b][h]
__device__ float g_k2 [(long)T * S * B * H];   // transformed keys [t][s][b][h]
__device__ float g_hA [S * B * H];
__device__ float g_hB [S * B * H];
__device__ float g_c  [S * B * H];
__device__ float g_inp[L * B];
__device__ float g_outs[(long)L * S * B];
// small precomputed tensors
__device__ float g_M1   [S * H * H];   // Wq^T @ Wk per stream
__device__ float g_u    [S * H];       // Wout^T @ wf2
__device__ float g_wbqk [S * H];       // bq^T @ Wk
__device__ float g_wvu  [S * H];       // u^T @ Wv
__device__ float g_k2b  [S * H];       // Wq^T @ bk
__device__ float g_cbqk [S];           // bq . bk
__device__ float g_cvu  [S];           // u . bv
__device__ float g_c1   [S];           // wf2.b_out + b_fcout
__device__ float g_bqk  [(long)T * S * B];  // per-key score bias
__device__ float g_vu   [(long)T * S * B];  // per-key value scalar

__device__ __forceinline__ float sigf(float x) { return 1.f / (1.f + __expf(-x)); }

// ---------------- prep: zero state, build teacher-forced decoder inputs ----------------
__global__ void prep_kernel(const float* __restrict__ x, const float* __restrict__ tgt) {
    int i = blockIdx.x * blockDim.x + threadIdx.x;
    if (i < S * B * H) { g_hA[i] = 0.f; g_hB[i] = 0.f; g_c[i] = 0.f; }
    if (i < L * B) {
        int l = i / B, b = i % B;
        g_inp[i] = (l == 0) ? x[(long)b * 96 * F + 95 * F + 0]
                            : tgt[(long)b * L + (l - 1)];
    }
}

// ---------------- precompute A: u, w_bqk, k2bias ----------------
__global__ void pc_a(const float* __restrict__ Wout, const float* __restrict__ Wfcout,
                     const float* __restrict__ Win,  const float* __restrict__ b_in) {
    int t = blockIdx.x * blockDim.x + threadIdx.x;
    if (t >= S * H) return;
    int s = t >> 8, e = t & 255;
    const float* wf2 = Wfcout + s * 2 * H + H;
    const float* Wo  = Wout + (long)s * H * H;
    float u = 0.f;
    for (int o = 0; o < H; o++) u += wf2[o] * Wo[o * H + e];
    g_u[t] = u;
    const float* bq = b_in + s * 3 * H;
    const float* bk = bq + H;
    const float* Wq = Win + (long)s * 3 * H * H;
    const float* Wk = Wq + H * H;
    float wb = 0.f, kb = 0.f;
    for (int e2 = 0; e2 < H; e2++) {
        wb += bq[e2] * Wk[e2 * H + e];
        kb += Wq[e2 * H + e] * bk[e2];
    }
    g_wbqk[t] = wb;
    g_k2b[t]  = kb;
}

// ---------------- precompute B: w_vu + scalar constants (needs g_u) ----------------
__global__ void pc_b(const float* __restrict__ Win, const float* __restrict__ b_in,
                     const float* __restrict__ Wfcout, const float* __restrict__ b_fcout,
                     const float* __restrict__ b_out) {
    int t = blockIdx.x * blockDim.x + threadIdx.x;
    if (t >= S * H) return;
    int s = t >> 8, h = t & 255;
    const float* Wv = Win + (long)s * 3 * H * H + 2 * H * H;
    float wv = 0.f;
    for (int e = 0; e < H; e++) wv += g_u[s * H + e] * Wv[e * H + h];
    g_wvu[t] = wv;
    if (h == 0) {
        const float* bq = b_in + s * 3 * H;
        const float* bk = bq + H;
        const float* bv = bq + 2 * H;
        const float* wf2 = Wfcout + s * 2 * H + H;
        const float* bo  = b_out + s * H;
        float cvu = 0.f, cb = 0.f, c1 = 0.f;
        for (int e = 0; e < H; e++) {
            cvu += g_u[s * H + e] * bv[e];
            cb  += bq[e] * bk[e];
            c1  += wf2[e] * bo[e];
        }
        g_cvu[s]  = cvu;
        g_cbqk[s] = cb;
        g_c1[s]   = c1 + b_fcout[s];
    }
}

// ---------------- precompute M1[s] = Wq^T @ Wk  (tiled small GEMM) ----------------
__global__ void pc_m1(const float* __restrict__ Win) {
    __shared__ float tq[16][17];
    __shared__ float tk[16][17];
    int s = blockIdx.z;
    const float* Wq = Win + (long)s * 3 * H * H;
    const float* Wk = Wq + H * H;
    int tyy = threadIdx.y, txx = threadIdx.x;
    int hq = blockIdx.y * 16 + tyy;
    int hk = blockIdx.x * 16 + txx;
    float acc = 0.f;
    for (int e0 = 0; e0 < H; e0 += 16) {
        tq[tyy][txx] = Wq[(e0 + tyy) * H + blockIdx.y * 16 + txx];
        tk[tyy][txx] = Wk[(e0 + tyy) * H + hk];
        __syncthreads();
#pragma unroll
        for (int ee = 0; ee < 16; ee++)
            acc = fmaf(tq[ee][tyy], tk[ee][txx], acc);
        __syncthreads();
    }
    g_M1[(long)s * H * H + hq * H + hk] = acc;
}

// ---------------- generic batched tiled GEMM (from R1) ----------------
#define BM 64
#define BN 64
#define BK 16
#define SMP 68

__global__ void gemm_k(
    const float* __restrict__ A, long sAz, int lda,
    const float* __restrict__ W, long sWz, int ldw,
    const float* __restrict__ b1, const float* __restrict__ b2, long sBz,
    float* __restrict__ C, long sCz, int ldc,
    int K, int wdiv)
{
    __shared__ float As[BK][SMP];
    __shared__ float Ws[BK][SMP];

    int z  = blockIdx.z;
    int wi = (z / wdiv) & 7;

    A += (long)z * sAz + (long)blockIdx.y * BM * lda;
    W += (long)wi * sWz + (long)blockIdx.x * BN * ldw;
    C += (long)z * sCz + (long)blockIdx.y * BM * ldc + blockIdx.x * BN;
    if (b1) b1 += (long)wi * sBz + blockIdx.x * BN;
    if (b2) b2 += (long)wi * sBz + blockIdx.x * BN;

    int t  = threadIdx.x;
    int lr = t >> 2;
    int lk = (t & 3) * 4;
    int tx = t & 15, ty = t >> 4;

    float acc[4][4];
#pragma unroll
    for (int i = 0; i < 4; i++)
#pragma unroll
        for (int j = 0; j < 4; j++) acc[i][j] = 0.f;

    for (int k0 = 0; k0 < K; k0 += BK) {
#pragma unroll
        for (int u = 0; u < 4; u++) {
            int k = k0 + lk + u;
            As[lk + u][lr] = (k < K) ? A[(long)lr * lda + k] : 0.f;
            Ws[lk + u][lr] = (k < K) ? W[(long)lr * ldw + k] : 0.f;
        }
        __syncthreads();
#pragma unroll
        for (int kk = 0; kk < BK; kk++) {
            float4 av = *(const float4*)&As[kk][ty * 4];
            float4 wv = *(const float4*)&Ws[kk][tx * 4];
            float a[4] = {av.x, av.y, av.z, av.w};
            float w[4] = {wv.x, wv.y, wv.z, wv.w};
#pragma unroll
            for (int i = 0; i < 4; i++)
#pragma unroll
                for (int j = 0; j < 4; j++)
                    acc[i][j] = fmaf(a[i], w[j], acc[i][j]);
        }
        __syncthreads();
    }

#pragma unroll
    for (int i = 0; i < 4; i++) {
        int m = ty * 4 + i;
#pragma unroll
        for (int j = 0; j < 4; j++) {
            int n = tx * 4 + j;
            float v = acc[i][j];
            if (b1) v += b1[n];
            if (b2) v += b2[n];
            C[(long)m * ldc + n] = v;
        }
    }
}

// ---------------- fused gates GEMM + LSTM cell ----------------
// Block: 64 m-rows x 32 j-cols x 4 gates; 256 threads; double-buffered smem.
// gates[q] = hin . Whh[q*H+j] (+b1+b2) (+add[b][q*H+j]) (+rvec[b]*cvec[q*H+j])
// then c,h update; h -> hout (+encout).
__global__ void __launch_bounds__(256) gates_lstm_kernel(
    const float* __restrict__ hin, float* __restrict__ hout,
    const float* __restrict__ Whh,
    const float* __restrict__ b1, const float* __restrict__ b2,
    const float* __restrict__ add, long sAddz,
    const float* __restrict__ rvec, const float* __restrict__ cvec,
    float* __restrict__ encout)
{
    __shared__ float As[2][16][66];
    __shared__ float Ws[2][4][16][36];

    const int s  = blockIdx.z;
    const int m0 = blockIdx.y * 64;
    const int j0 = blockIdx.x * 32;
    const int t  = threadIdx.x;
    const int tx = t & 7;     // j quad (0..7)
    const int ty = t >> 3;    // m pair (0..31)

    const float* A = hin + ((long)s * B + m0) * H;
    const float* W = Whh + (long)s * (4 * H * H);

    const int ar = (t * 2) >> 4;       // 0..31
    const int ak = (t * 2) & 15;       // even
    const int wq = (t * 4) >> 9;       // 0..1
    const int wr = ((t * 4) & 511) >> 4;
    const int wk = (t * 4) & 15;       // multiple of 4

    const float* Ag0 = A + (long)ar * H + ak;
    const float* Ag1 = A + (long)(ar + 32) * H + ak;
    const float* Wg0 = W + ((long)(wq * H + j0 + wr)) * H + wk;
    const float* Wg1 = W + ((long)((wq + 2) * H + j0 + wr)) * H + wk;

    float2 ra0, ra1;
    float4 rw0, rw1;
    ra0 = *(const float2*)Ag0;  ra1 = *(const float2*)Ag1;
    rw0 = *(const float4*)Wg0;  rw1 = *(const float4*)Wg1;

    float acc[4][2][4];
#pragma unroll
    for (int q = 0; q < 4; q++)
#pragma unroll
        for (int i = 0; i < 2; i++)
#pragma unroll
            for (int j = 0; j < 4; j++) acc[q][i][j] = 0.f;

#define STORE_TILE(bf) do {                                                   \
        As[bf][ak][ar]        = ra0.x; As[bf][ak + 1][ar]        = ra0.y;     \
        As[bf][ak][ar + 32]   = ra1.x; As[bf][ak + 1][ar + 32]   = ra1.y;     \
        Ws[bf][wq][wk + 0][wr] = rw0.x; Ws[bf][wq][wk + 1][wr] = rw0.y;       \
        Ws[bf][wq][wk + 2][wr] = rw0.z; Ws[bf][wq][wk + 3][wr] = rw0.w;       \
        Ws[bf][wq + 2][wk + 0][wr] = rw1.x; Ws[bf][wq + 2][wk + 1][wr] = rw1.y; \
        Ws[bf][wq + 2][wk + 2][wr] = rw1.z; Ws[bf][wq + 2][wk + 3][wr] = rw1.w; \
    } while (0)

    STORE_TILE(0);
    __syncthreads();

    for (int it = 0; it < 16; ++it) {
        int cur = it & 1;
        if (it < 15) {
            int k0 = (it + 1) * 16;
            ra0 = *(const float2*)(Ag0 + k0);
            ra1 = *(const float2*)(Ag1 + k0);
            rw0 = *(const float4*)(Wg0 + k0);
            rw1 = *(const float4*)(Wg1 + k0);
        }
#pragma unroll
        for (int kk = 0; kk < 16; kk++) {
            float2 av = *(const float2*)&As[cur][kk][ty * 2];
#pragma unroll
            for (int q = 0; q < 4; q++) {
                float4 wv = *(const float4*)&Ws[cur][q][kk][tx * 4];
                acc[q][0][0] = fmaf(av.x, wv.x, acc[q][0][0]);
                acc[q][0][1] = fmaf(av.x, wv.y, acc[q][0][1]);
                acc[q][0][2] = fmaf(av.x, wv.z, acc[q][0][2]);
                acc[q][0][3] = fmaf(av.x, wv.w, acc[q][0][3]);
                acc[q][1][0] = fmaf(av.y, wv.x, acc[q][1][0]);
                acc[q][1][1] = fmaf(av.y, wv.y, acc[q][1][1]);
                acc[q][1][2] = fmaf(av.y, wv.z, acc[q][1][2]);
                acc[q][1][3] = fmaf(av.y, wv.w, acc[q][1][3]);
            }
        }
        if (it < 15) STORE_TILE(cur ^ 1);
        __syncthreads();
    }
#undef STORE_TILE

    // ---- epilogue: biases + rank-1 + add, then LSTM ----
    float bias[4][4];
    float cv[4][4];
#pragma unroll
    for (int q = 0; q < 4; q++) {
        int gg = q * H + j0 + tx * 4;
        float4 v = make_float4(0.f, 0.f, 0.f, 0.f);
        if (b1) {
            float4 x = *(const float4*)&b1[s * G + gg];
            v.x += x.x; v.y += x.y; v.z += x.z; v.w += x.w;
        }
        if (b2) {
            float4 x = *(const float4*)&b2[s * G + gg];
            v.x += x.x; v.y += x.y; v.z += x.z; v.w += x.w;
        }
        bias[q][0] = v.x; bias[q][1] = v.y; bias[q][2] = v.z; bias[q][3] = v.w;
        if (cvec) {
            float4 x = *(const float4*)&cvec[s * G + gg];
            cv[q][0] = x.x; cv[q][1] = x.y; cv[q][2] = x.z; cv[q][3] = x.w;
        }
    }
    float rv[2] = {0.f, 0.f};
    if (rvec) { rv[0] = rvec[m0 + ty * 2]; rv[1] = rvec[m0 + ty * 2 + 1]; }

#pragma unroll
    for (int i = 0; i < 2; i++) {
        int bb = m0 + ty * 2 + i;
        long base = ((long)s * B + bb) * H + j0 + tx * 4;
        float gate[4][4];
#pragma unroll
        for (int q = 0; q < 4; q++) {
            float av[4] = {0.f, 0.f, 0.f, 0.f};
            if (add) {
                float4 x = *(const float4*)&add[(long)s * sAddz + (long)bb * G + q * H + j0 + tx * 4];
                av[0] = x.x; av[1] = x.y; av[2] = x.z; av[3] = x.w;
            }
#pragma unroll
            for (int j = 0; j < 4; j++) {
                float v = acc[q][i][j] + bias[q][j] + av[j];
                if (rvec) v = fmaf(rv[i], cv[q][j], v);
                gate[q][j] = v;
            }
        }
        float4 cold = *(const float4*)&g_c[base];
        float co[4] = {cold.x, cold.y, cold.z, cold.w};
        float4 cn, hn;
        float cnv[4], hnv[4];
#pragma unroll
        for (int j = 0; j < 4; j++) {
            float c_ = sigf(gate[1][j]) * co[j] + sigf(gate[0][j]) * tanhf(gate[2][j]);
            float h_ = sigf(gate[3][j]) * tanhf(c_);
            cnv[j] = c_; hnv[j] = h_;
        }
        cn = make_float4(cnv[0], cnv[1], cnv[2], cnv[3]);
        hn = make_float4(hnv[0], hnv[1], hnv[2], hnv[3]);
        *(float4*)&g_c[base] = cn;
        *(float4*)&hout[base] = hn;
        if (encout) *(float4*)&encout[base] = hn;
    }
}

// ---------------- per-(t,s,b) scalars: bqk, vu  (after encoder) ----------------
__global__ void pc_scal_kernel() {
    int gtid = blockIdx.x * blockDim.x + threadIdx.x;
    int warp = gtid >> 5;                  // (t*S+s)*B + b
    int lane = threadIdx.x & 31;
    if (warp >= T * S * B) return;
    int s = (warp >> 10) & 7;

    const float* ep = g_enc + (long)warp * H;
    const float* wb = g_wbqk + s * H;
    const float* wv = g_wvu + s * H;
    float db = 0.f, dv = 0.f;
#pragma unroll
    for (int u = 0; u < 2; u++) {
        int e = lane * 4 + u * 128;
        float4 ev = *(const float4*)&ep[e];
        float4 b4 = *(const float4*)&wb[e];
        float4 v4 = *(const float4*)&wv[e];
        db += ev.x * b4.x + ev.y * b4.y + ev.z * b4.z + ev.w * b4.w;
        dv += ev.x * v4.x + ev.y * v4.y + ev.z * v4.z + ev.w * v4.w;
    }
#pragma unroll
    for (int off = 16; off; off >>= 1) {
        db += __shfl_xor_sync(0xffffffffu, db, off);
        dv += __shfl_xor_sync(0xffffffffu, dv, off);
    }
    if (lane == 0) {
        g_bqk[warp] = db + g_cbqk[s];
        g_vu[warp]  = dv + g_cvu[s];
    }
}

// ---------------- decoder tail: scores/softmax/output, warp per (s,b) ----------------
__global__ void dec_attn_kernel(const float* __restrict__ hcur,
                                const float* __restrict__ Wfcout, int l) {
    int gtid = blockIdx.x * blockDim.x + threadIdx.x;
    int warp = gtid >> 5;                  // s*B + b
    int lane = threadIdx.x & 31;
    if (warp >= S * B) return;
    int s = warp >> 10;

    const float* hp = hcur + (long)warp * H;
    float4 h0 = *(const float4*)&hp[lane * 4];
    float4 h1 = *(const float4*)&hp[128 + lane * 4];

    const float* wf = Wfcout + s * 2 * H;
    float4 w0 = *(const float4*)&wf[lane * 4];
    float4 w1 = *(const float4*)&wf[128 + lane * 4];

    float red[T + 1];
    red[T] = h0.x * w0.x + h0.y * w0.y + h0.z * w0.z + h0.w * w0.w
           + h1.x * w1.x + h1.y * w1.y + h1.z * w1.z + h1.w * w1.w;

#pragma unroll
    for (int tt = 0; tt < T; tt++) {
        const float* kp = g_k2 + ((long)tt * S * B + warp) * H;
        float4 k0 = *(const float4*)&kp[lane * 4];
        float4 k1 = *(const float4*)&kp[128 + lane * 4];
        red[tt] = h0.x * k0.x + h0.y * k0.y + h0.z * k0.z + h0.w * k0.w
                + h1.x * k1.x + h1.y * k1.y + h1.z * k1.z + h1.w * k1.w;
    }
#pragma unroll
    for (int r = 0; r < T + 1; r++) {
        float v = red[r];
#pragma unroll
        for (int off = 16; off; off >>= 1) v += __shfl_xor_sync(0xffffffffu, v, off);
        red[r] = v;
    }

    float sc[T];
    float mx = -1e30f;
#pragma unroll
    for (int tt = 0; tt < T; tt++) {
        float v = (red[tt] + g_bqk[(long)tt * S * B + warp]) * 0.0625f;
        sc[tt] = v;
        mx = fmaxf(mx, v);
    }
    float sum = 0.f;
#pragma unroll
    for (int tt = 0; tt < T; tt++) { sc[tt] = __expf(sc[tt] - mx); sum += sc[tt]; }
    float inv = 1.f / sum;
    float ctxdot = 0.f;
#pragma unroll
    for (int tt = 0; tt < T; tt++)
        ctxdot = fmaf(sc[tt] * inv, g_vu[(long)tt * S * B + warp], ctxdot);

    if (lane == 0)
        g_outs[(long)l * S * B + warp] = red[T] + ctxdot + g_c1[s];
}

// ---------------- final 8->1 mix ----------------
__global__ void final_kernel(const float* __restrict__ Wfc, const float* __restrict__ bfc,
                             float* __restrict__ out) {
    int i = blockIdx.x * blockDim.x + threadIdx.x;   // i = b*L + l
    if (i >= B * L) return;
    int b = i / L, l = i % L;
    float acc = bfc[0];
#pragma unroll
    for (int s = 0; s < S; s++)
        acc += g_outs[(long)l * S * B + (long)s * B + b] * Wfc[s];
    out[i] = acc;
}

// ---------------- host launch ----------------
extern "C" void kernel_launch(void* const* d_in, const int* in_sizes, int n_in,
                              void* d_out, int out_size) {
    const float* x       = (const float*)d_in[0];
    const float* tgt     = (const float*)d_in[1];
    const float* W_ih_e  = (const float*)d_in[2];
    const float* W_hh_e  = (const float*)d_in[3];
    const float* b_ih_e  = (const float*)d_in[4];
    const float* b_hh_e  = (const float*)d_in[5];
    const float* W_ih_d  = (const float*)d_in[6];
    const float* W_hh_d  = (const float*)d_in[7];
    const float* b_ih_d  = (const float*)d_in[8];
    const float* b_hh_d  = (const float*)d_in[9];
    const float* W_in    = (const float*)d_in[10];
    const float* b_in    = (const float*)d_in[11];
    const float* W_out   = (const float*)d_in[12];
    const float* b_out   = (const float*)d_in[13];
    const float* W_fcout = (const float*)d_in[14];
    const float* b_fcout = (const float*)d_in[15];
    const float* W_fc    = (const float*)d_in[16];
    const float* b_fc    = (const float*)d_in[17];
    float* out = (float*)d_out;

    float *Gin, *enc, *k2, *hA, *hB, *inp, *M1, *k2b;
    cudaGetSymbolAddress((void**)&Gin, g_Gin);
    cudaGetSymbolAddress((void**)&enc, g_enc);
    cudaGetSymbolAddress((void**)&k2,  g_k2);
    cudaGetSymbolAddress((void**)&hA,  g_hA);
    cudaGetSymbolAddress((void**)&hB,  g_hB);
    cudaGetSymbolAddress((void**)&inp, g_inp);
    cudaGetSymbolAddress((void**)&M1,  g_M1);
    cudaGetSymbolAddress((void**)&k2b, g_k2b);

    prep_kernel<<<(S * B * H + 255) / 256, 256>>>(x, tgt);
    pc_a<<<(S * H + 255) / 256, 256>>>(W_out, W_fcout, W_in, b_in);
    pc_b<<<(S * H + 255) / 256, 256>>>(W_in, b_in, W_fcout, b_fcout, b_out);
    pc_m1<<<dim3(16, 16, 8), dim3(16, 16)>>>(W_in);

    // 1) encoder input projections (+both biases): Gin[z=s*12+t][b][g]
    gemm_k<<<dim3(G / 64, B / 64, 96), 256>>>(
        x, (long)F, 96 * F,
        W_ih_e, (long)G * F, F,
        b_ih_e, b_hh_e, G,
        Gin, (long)B * G, G, F, 12);

    // 2) encoder recurrence (fused gates GEMM + LSTM), ping-pong h
    float* hin = hA; float* hout = hB;
    for (int tt = 0; tt < T; tt++) {
        gates_lstm_kernel<<<dim3(H / 32, B / 64, S), 256>>>(
            hin, hout, W_hh_e,
            nullptr, nullptr,
            Gin + (long)tt * B * G, 12l * B * G,
            nullptr, nullptr,
            enc + (long)tt * S * B * H);
        float* tmp = hin; hin = hout; hout = tmp;
    }

    // 3) per-key scalars + transformed keys
    pc_scal_kernel<<<(T * S * B * 32 + 255) / 256, 256>>>();
    gemm_k<<<dim3(H / 64, B / 64, T * S), 256>>>(
        enc, (long)B * H, H,
        M1, (long)H * H, H,
        k2b, nullptr, H,
        k2, (long)B * H, H, H, 1);

    // 4) decoder: 48 steps x 2 kernels
    for (int l = 0; l < L; l++) {
        gates_lstm_kernel<<<dim3(H / 32, B / 64, S), 256>>>(
            hin, hout, W_hh_d,
            b_ih_d, b_hh_d,
            nullptr, 0,
            inp + (long)l * B, W_ih_d,
            nullptr);
        float* tmp = hin; hin = hout; hout = tmp;
        dec_attn_kernel<<<(S * B * 32 + 255) / 256, 256>>>(hin, W_fcout, l);
    }

    // 5) final mix
    final_kernel<<<(B * L + 255) / 256, 256>>>(W_fc, b_fc, out);
}

// round 3
// speedup vs baseline: 3.9349x; 3.1776x over previous
#include <cuda_runtime.h>
#include <math.h>

// ---------------- problem constants ----------------
#define S   8
#define T   12
#define H   256
#define F   316
#define B   1024
#define L   48
#define G   1024      // 4*H

// ---------------- scratch (device globals; no allocs allowed) ----------------
__device__ float g_Gin[96l * B * G];           // encoder input gates [s*12+t][b][g]
__device__ float g_enc[(long)T * S * B * H];   // encoder outputs [t][s][b][h]
__device__ float g_k2 [(long)T * S * B * H];   // transformed keys [t][s][b][h]
__device__ float g_hA [S * B * H];
__device__ float g_hB [S * B * H];
__device__ float g_c  [S * B * H];
__device__ float g_inp[L * B];
__device__ float g_outs[(long)L * S * B];
// small precomputed tensors
__device__ float g_M1   [S * H * H];   // Wq^T @ Wk per stream
__device__ float g_u    [S * H];       // Wout^T @ wf2
__device__ float g_wbqk [S * H];       // bq^T @ Wk
__device__ float g_wvu  [S * H];       // u^T @ Wv
__device__ float g_k2b  [S * H];       // Wq^T @ bk
__device__ float g_cbqk [S];
__device__ float g_cvu  [S];
__device__ float g_c1   [S];
__device__ float g_bqk  [(long)T * S * B];
__device__ float g_vu   [(long)T * S * B];

__device__ __forceinline__ float sigf(float x) { return 1.f / (1.f + __expf(-x)); }

__device__ __forceinline__ unsigned f2tf(float f) {
    unsigned u;
    asm("cvt.rna.tf32.f32 %0, %1;" : "=r"(u) : "f"(f));
    return u;
}

__device__ __forceinline__ void mma_tf32(float c[4],
    unsigned a0, unsigned a1, unsigned a2, unsigned a3,
    unsigned b0, unsigned b1)
{
    asm volatile(
        "mma.sync.aligned.m16n8k8.row.col.f32.tf32.tf32.f32 "
        "{%0,%1,%2,%3}, {%4,%5,%6,%7}, {%8,%9}, {%0,%1,%2,%3};"
        : "+f"(c[0]), "+f"(c[1]), "+f"(c[2]), "+f"(c[3])
        : "r"(a0), "r"(a1), "r"(a2), "r"(a3), "r"(b0), "r"(b1));
}

// ---------------- prep ----------------
__global__ void prep_kernel(const float* __restrict__ x, const float* __restrict__ tgt) {
    int i = blockIdx.x * blockDim.x + threadIdx.x;
    if (i < S * B * H) { g_hA[i] = 0.f; g_hB[i] = 0.f; g_c[i] = 0.f; }
    if (i < L * B) {
        int l = i / B, b = i % B;
        g_inp[i] = (l == 0) ? x[(long)b * 96 * F + 95 * F + 0]
                            : tgt[(long)b * L + (l - 1)];
    }
}

// ---------------- small precomputes (one-time) ----------------
__global__ void pc_a(const float* __restrict__ Wout, const float* __restrict__ Wfcout,
                     const float* __restrict__ Win,  const float* __restrict__ b_in) {
    int t = blockIdx.x * blockDim.x + threadIdx.x;
    if (t >= S * H) return;
    int s = t >> 8, e = t & 255;
    const float* wf2 = Wfcout + s * 2 * H + H;
    const float* Wo  = Wout + (long)s * H * H;
    float u = 0.f;
    for (int o = 0; o < H; o++) u += wf2[o] * Wo[o * H + e];
    g_u[t] = u;
    const float* bq = b_in + s * 3 * H;
    const float* bk = bq + H;
    const float* Wq = Win + (long)s * 3 * H * H;
    const float* Wk = Wq + H * H;
    float wb = 0.f, kb = 0.f;
    for (int e2 = 0; e2 < H; e2++) {
        wb += bq[e2] * Wk[e2 * H + e];
        kb += Wq[e2 * H + e] * bk[e2];
    }
    g_wbqk[t] = wb;
    g_k2b[t]  = kb;
}

__global__ void pc_b(const float* __restrict__ Win, const float* __restrict__ b_in,
                     const float* __restrict__ Wfcout, const float* __restrict__ b_fcout,
                     const float* __restrict__ b_out) {
    int t = blockIdx.x * blockDim.x + threadIdx.x;
    if (t >= S * H) return;
    int s = t >> 8, h = t & 255;
    const float* Wv = Win + (long)s * 3 * H * H + 2 * H * H;
    float wv = 0.f;
    for (int e = 0; e < H; e++) wv += g_u[s * H + e] * Wv[e * H + h];
    g_wvu[t] = wv;
    if (h == 0) {
        const float* bq = b_in + s * 3 * H;
        const float* bk = bq + H;
        const float* bv = bq + 2 * H;
        const float* wf2 = Wfcout + s * 2 * H + H;
        const float* bo  = b_out + s * H;
        float cvu = 0.f, cb = 0.f, c1 = 0.f;
        for (int e = 0; e < H; e++) {
            cvu += g_u[s * H + e] * bv[e];
            cb  += bq[e] * bk[e];
            c1  += wf2[e] * bo[e];
        }
        g_cvu[s]  = cvu;
        g_cbqk[s] = cb;
        g_c1[s]   = c1 + b_fcout[s];
    }
}

__global__ void pc_m1(const float* __restrict__ Win) {
    __shared__ float tq[16][17];
    __shared__ float tk[16][17];
    int s = blockIdx.z;
    const float* Wq = Win + (long)s * 3 * H * H;
    const float* Wk = Wq + H * H;
    int tyy = threadIdx.y, txx = threadIdx.x;
    int hq = blockIdx.y * 16 + tyy;
    int hk = blockIdx.x * 16 + txx;
    float acc = 0.f;
    for (int e0 = 0; e0 < H; e0 += 16) {
        tq[tyy][txx] = Wq[(e0 + tyy) * H + blockIdx.y * 16 + txx];
        tk[tyy][txx] = Wk[(e0 + tyy) * H + hk];
        __syncthreads();
#pragma unroll
        for (int ee = 0; ee < 16; ee++)
            acc = fmaf(tq[ee][tyy], tk[ee][txx], acc);
        __syncthreads();
    }
    g_M1[(long)s * H * H + hq * H + hk] = acc;
}

// ================= generic tf32 tensor-core GEMM =================
// C[z][m][n] = sum_k A[z][m][k] * W[wi][n][k] + b1[n] + b2[n]
// block: 256 thr / 8 warps, tile 128x128, warp tile m32 x n64, BK=16
__global__ void __launch_bounds__(256) gemm_tc(
    const float* __restrict__ Ag, long sAz, int lda,
    const float* __restrict__ Wg, long sWz, int ldw,
    const float* __restrict__ b1, const float* __restrict__ b2, long sBz,
    float* __restrict__ C, long sCz, int ldc,
    int K, int wdiv)
{
    __shared__ unsigned As[2][128 * 20];
    __shared__ unsigned Ws[2][128 * 20];

    const int z  = blockIdx.z;
    const int wi = (z / wdiv) & 7;
    const int m0 = blockIdx.y * 128;
    const int n0 = blockIdx.x * 128;

    const float* Ap = Ag + (long)z * sAz + (long)m0 * lda;
    const float* Wp = Wg + (long)wi * sWz + (long)n0 * ldw;

    const int t = threadIdx.x;
    const int w = t >> 5, lane = t & 31;
    const int lq = lane >> 2, lr = lane & 3;
    const int wm = w & 3, wn = w >> 2;

    float4 pa[2], pw[2];

    auto ld = [&](int c) {
        int k0 = c * 16;
#pragma unroll
        for (int p = 0; p < 2; p++) {
            int i = t + 256 * p;
            int row = i >> 2, k4 = i & 3;
            int k = k0 + k4 * 4;
            if (k < K) {
                pa[p] = *(const float4*)(Ap + (long)row * lda + k);
                pw[p] = *(const float4*)(Wp + (long)row * ldw + k);
            } else {
                pa[p] = make_float4(0.f, 0.f, 0.f, 0.f);
                pw[p] = make_float4(0.f, 0.f, 0.f, 0.f);
            }
        }
    };
    auto st = [&](int bf) {
#pragma unroll
        for (int p = 0; p < 2; p++) {
            int i = t + 256 * p;
            int row = i >> 2, k4 = i & 3;
            uint4 ua = make_uint4(f2tf(pa[p].x), f2tf(pa[p].y), f2tf(pa[p].z), f2tf(pa[p].w));
            uint4 uw = make_uint4(f2tf(pw[p].x), f2tf(pw[p].y), f2tf(pw[p].z), f2tf(pw[p].w));
            *(uint4*)&As[bf][row * 20 + k4 * 4] = ua;
            *(uint4*)&Ws[bf][row * 20 + k4 * 4] = uw;
        }
    };

    float acc[2][8][4];
#pragma unroll
    for (int mt = 0; mt < 2; mt++)
#pragma unroll
        for (int nt = 0; nt < 8; nt++)
#pragma unroll
            for (int v = 0; v < 4; v++) acc[mt][nt][v] = 0.f;

    const int NC = (K + 15) / 16;
    ld(0); st(0);
    __syncthreads();

    for (int c = 0; c < NC; c++) {
        int cur = c & 1;
        if (c + 1 < NC) ld(c + 1);
#pragma unroll
        for (int k8s = 0; k8s < 2; k8s++) {
            int kb = k8s * 8;
            unsigned a[2][4];
#pragma unroll
            for (int mt = 0; mt < 2; mt++) {
                int r = wm * 32 + mt * 16 + lq;
                a[mt][0] = As[cur][r * 20 + kb + lr];
                a[mt][1] = As[cur][(r + 8) * 20 + kb + lr];
                a[mt][2] = As[cur][r * 20 + kb + lr + 4];
                a[mt][3] = As[cur][(r + 8) * 20 + kb + lr + 4];
            }
#pragma unroll
            for (int nt = 0; nt < 8; nt++) {
                int rn = wn * 64 + nt * 8 + lq;
                unsigned bb0 = Ws[cur][rn * 20 + kb + lr];
                unsigned bb1 = Ws[cur][rn * 20 + kb + lr + 4];
#pragma unroll
                for (int mt = 0; mt < 2; mt++)
                    mma_tf32(acc[mt][nt], a[mt][0], a[mt][1], a[mt][2], a[mt][3], bb0, bb1);
            }
        }
        if (c + 1 < NC) st(cur ^ 1);
        __syncthreads();
    }

    // epilogue
    C += (long)z * sCz;
#pragma unroll
    for (int mt = 0; mt < 2; mt++) {
#pragma unroll
        for (int nt = 0; nt < 8; nt++) {
#pragma unroll
            for (int rh = 0; rh < 2; rh++) {
                int m = m0 + wm * 32 + mt * 16 + lq + rh * 8;
                int n = n0 + wn * 64 + nt * 8 + lr * 2;
                float v0 = acc[mt][nt][rh * 2];
                float v1 = acc[mt][nt][rh * 2 + 1];
                if (b1) { v0 += b1[(long)wi * sBz + n]; v1 += b1[(long)wi * sBz + n + 1]; }
                if (b2) { v0 += b2[(long)wi * sBz + n]; v1 += b2[(long)wi * sBz + n + 1]; }
                float2 v = make_float2(v0, v1);
                *(float2*)&C[(long)m * ldc + n] = v;
            }
        }
    }
}

// ================= fused tf32 gates GEMM + LSTM =================
// block: 128 thr / 4 warps, tile 128(m=b) x [4 gates x 16 j], warp m32 x n64
// gates[q][b][j] = hin . Whh + b1 + b2 + add + rvec*cvec, then LSTM cell.
__global__ void __launch_bounds__(128) gates_lstm_tc(
    const float* __restrict__ hin, float* __restrict__ hout,
    const float* __restrict__ Whh,
    const float* __restrict__ b1, const float* __restrict__ b2,
    const float* __restrict__ add, long sAddz,
    const float* __restrict__ rvec, const float* __restrict__ cvec,
    float* __restrict__ encout)
{
    __shared__ unsigned As[2][128 * 20];
    __shared__ unsigned Ws[2][64 * 20];

    const int s  = blockIdx.z;
    const int m0 = blockIdx.y * 128;
    const int j0 = blockIdx.x * 16;

    const float* Ap = hin + ((long)s * B + m0) * H;
    const float* Wp = Whh + (long)s * (4 * H * H);

    const int t = threadIdx.x;
    const int w = t >> 5, lane = t & 31;
    const int lq = lane >> 2, lr = lane & 3;

    float4 pa[4], pw[2];

    auto ld = [&](int c) {
        int k0 = c * 16;
#pragma unroll
        for (int p = 0; p < 4; p++) {
            int i = t + 128 * p;
            int row = i >> 2, k4 = i & 3;
            pa[p] = *(const float4*)(Ap + (long)row * H + k0 + k4 * 4);
        }
#pragma unroll
        for (int p = 0; p < 2; p++) {
            int i = t + 128 * p;
            int r = i >> 2, k4 = i & 3;
            int wrow = (r >> 4) * H + j0 + (r & 15);
            pw[p] = *(const float4*)(Wp + (long)wrow * H + k0 + k4 * 4);
        }
    };
    auto st = [&](int bf) {
#pragma unroll
        for (int p = 0; p < 4; p++) {
            int i = t + 128 * p;
            int row = i >> 2, k4 = i & 3;
            uint4 u = make_uint4(f2tf(pa[p].x), f2tf(pa[p].y), f2tf(pa[p].z), f2tf(pa[p].w));
            *(uint4*)&As[bf][row * 20 + k4 * 4] = u;
        }
#pragma unroll
        for (int p = 0; p < 2; p++) {
            int i = t + 128 * p;
            int r = i >> 2, k4 = i & 3;
            uint4 u = make_uint4(f2tf(pw[p].x), f2tf(pw[p].y), f2tf(pw[p].z), f2tf(pw[p].w));
            *(uint4*)&Ws[bf][r * 20 + k4 * 4] = u;
        }
    };

    float acc[2][8][4];
#pragma unroll
    for (int mt = 0; mt < 2; mt++)
#pragma unroll
        for (int nt = 0; nt < 8; nt++)
#pragma unroll
            for (int v = 0; v < 4; v++) acc[mt][nt][v] = 0.f;

    ld(0); st(0);
    __syncthreads();

#pragma unroll 1
    for (int c = 0; c < 16; c++) {
        int cur = c & 1;
        if (c < 15) ld(c + 1);
#pragma unroll
        for (int k8s = 0; k8s < 2; k8s++) {
            int kb = k8s * 8;
            unsigned a[2][4];
#pragma unroll
            for (int mt = 0; mt < 2; mt++) {
                int r = w * 32 + mt * 16 + lq;
                a[mt][0] = As[cur][r * 20 + kb + lr];
                a[mt][1] = As[cur][(r + 8) * 20 + kb + lr];
                a[mt][2] = As[cur][r * 20 + kb + lr + 4];
                a[mt][3] = As[cur][(r + 8) * 20 + kb + lr + 4];
            }
#pragma unroll
            for (int nt = 0; nt < 8; nt++) {
                int rn = nt * 8 + lq;
                unsigned bb0 = Ws[cur][rn * 20 + kb + lr];
                unsigned bb1 = Ws[cur][rn * 20 + kb + lr + 4];
#pragma unroll
                for (int mt = 0; mt < 2; mt++)
                    mma_tf32(acc[mt][nt], a[mt][0], a[mt][1], a[mt][2], a[mt][3], bb0, bb1);
            }
        }
        if (c < 15) st(cur ^ 1);
        __syncthreads();
    }

    // ---- epilogue: biases + add + rank-1, then LSTM cell ----
    // n-tile nt = q*2 + i : gate q, j-subtile i; j = j0 + i*8 + lr*2 + {0,1}
#pragma unroll
    for (int mt = 0; mt < 2; mt++) {
#pragma unroll
        for (int rh = 0; rh < 2; rh++) {
            int b_row = m0 + w * 32 + mt * 16 + lq + rh * 8;
            long hbase = ((long)s * B + b_row) * H;
            float rv = rvec ? rvec[b_row] : 0.f;
#pragma unroll
            for (int i = 0; i < 2; i++) {
                int j = j0 + i * 8 + lr * 2;
                float gate[4][2];
#pragma unroll
                for (int q = 0; q < 4; q++) {
                    int gg = q * H + j;
                    float v0 = acc[mt][q * 2 + i][rh * 2];
                    float v1 = acc[mt][q * 2 + i][rh * 2 + 1];
                    if (b1) {
                        float2 x = *(const float2*)&b1[s * G + gg];
                        v0 += x.x; v1 += x.y;
                    }
                    if (b2) {
                        float2 x = *(const float2*)&b2[s * G + gg];
                        v0 += x.x; v1 += x.y;
                    }
                    if (add) {
                        float2 x = *(const float2*)&add[(long)s * sAddz + (long)b_row * G + gg];
                        v0 += x.x; v1 += x.y;
                    }
                    if (cvec) {
                        float2 x = *(const float2*)&cvec[s * G + gg];
                        v0 = fmaf(rv, x.x, v0); v1 = fmaf(rv, x.y, v1);
                    }
                    gate[q][0] = v0; gate[q][1] = v1;
                }
                float2 cold = *(const float2*)&g_c[hbase + j];
                float co[2] = {cold.x, cold.y};
                float hn[2], cn[2];
#pragma unroll
                for (int d = 0; d < 2; d++) {
                    float c_ = sigf(gate[1][d]) * co[d] + sigf(gate[0][d]) * tanhf(gate[2][d]);
                    float h_ = sigf(gate[3][d]) * tanhf(c_);
                    cn[d] = c_; hn[d] = h_;
                }
                *(float2*)&g_c[hbase + j] = make_float2(cn[0], cn[1]);
                *(float2*)&hout[hbase + j] = make_float2(hn[0], hn[1]);
                if (encout) *(float2*)&encout[hbase + j] = make_float2(hn[0], hn[1]);
            }
        }
    }
}

// ---------------- per-(t,s,b) scalars ----------------
__global__ void pc_scal_kernel() {
    int gtid = blockIdx.x * blockDim.x + threadIdx.x;
    int warp = gtid >> 5;
    int lane = threadIdx.x & 31;
    if (warp >= T * S * B) return;
    int s = (warp >> 10) & 7;

    const float* ep = g_enc + (long)warp * H;
    const float* wb = g_wbqk + s * H;
    const float* wv = g_wvu + s * H;
    float db = 0.f, dv = 0.f;
#pragma unroll
    for (int u = 0; u < 2; u++) {
        int e = lane * 4 + u * 128;
        float4 ev = *(const float4*)&ep[e];
        float4 b4 = *(const float4*)&wb[e];
        float4 v4 = *(const float4*)&wv[e];
        db += ev.x * b4.x + ev.y * b4.y + ev.z * b4.z + ev.w * b4.w;
        dv += ev.x * v4.x + ev.y * v4.y + ev.z * v4.z + ev.w * v4.w;
    }
#pragma unroll
    for (int off = 16; off; off >>= 1) {
        db += __shfl_xor_sync(0xffffffffu, db, off);
        dv += __shfl_xor_sync(0xffffffffu, dv, off);
    }
    if (lane == 0) {
        g_bqk[warp] = db + g_cbqk[s];
        g_vu[warp]  = dv + g_cvu[s];
    }
}

// ---------------- decoder tail ----------------
__global__ void dec_attn_kernel(const float* __restrict__ hcur,
                                const float* __restrict__ Wfcout, int l) {
    int gtid = blockIdx.x * blockDim.x + threadIdx.x;
    int warp = gtid >> 5;
    int lane = threadIdx.x & 31;
    if (warp >= S * B) return;
    int s = warp >> 10;

    const float* hp = hcur + (long)warp * H;
    float4 h0 = *(const float4*)&hp[lane * 4];
    float4 h1 = *(const float4*)&hp[128 + lane * 4];

    const float* wf = Wfcout + s * 2 * H;
    float4 w0 = *(const float4*)&wf[lane * 4];
    float4 w1 = *(const float4*)&wf[128 + lane * 4];

    float red[T + 1];
    red[T] = h0.x * w0.x + h0.y * w0.y + h0.z * w0.z + h0.w * w0.w
           + h1.x * w1.x + h1.y * w1.y + h1.z * w1.z + h1.w * w1.w;

#pragma unroll
    for (int tt = 0; tt < T; tt++) {
        const float* kp = g_k2 + ((long)tt * S * B + warp) * H;
        float4 k0 = *(const float4*)&kp[lane * 4];
        float4 k1 = *(const float4*)&kp[128 + lane * 4];
        red[tt] = h0.x * k0.x + h0.y * k0.y + h0.z * k0.z + h0.w * k0.w
                + h1.x * k1.x + h1.y * k1.y + h1.z * k1.z + h1.w * k1.w;
    }
#pragma unroll
    for (int r = 0; r < T + 1; r++) {
        float v = red[r];
#pragma unroll
        for (int off = 16; off; off >>= 1) v += __shfl_xor_sync(0xffffffffu, v, off);
        red[r] = v;
    }

    float sc[T];
    float mx = -1e30f;
#pragma unroll
    for (int tt = 0; tt < T; tt++) {
        float v = (red[tt] + g_bqk[(long)tt * S * B + warp]) * 0.0625f;
        sc[tt] = v;
        mx = fmaxf(mx, v);
    }
    float sum = 0.f;
#pragma unroll
    for (int tt = 0; tt < T; tt++) { sc[tt] = __expf(sc[tt] - mx); sum += sc[tt]; }
    float inv = 1.f / sum;
    float ctxdot = 0.f;
#pragma unroll
    for (int tt = 0; tt < T; tt++)
        ctxdot = fmaf(sc[tt] * inv, g_vu[(long)tt * S * B + warp], ctxdot);

    if (lane == 0)
        g_outs[(long)l * S * B + warp] = red[T] + ctxdot + g_c1[s];
}

// ---------------- final 8->1 mix ----------------
__global__ void final_kernel(const float* __restrict__ Wfc, const float* __restrict__ bfc,
                             float* __restrict__ out) {
    int i = blockIdx.x * blockDim.x + threadIdx.x;
    if (i >= B * L) return;
    int b = i / L, l = i % L;
    float acc = bfc[0];
#pragma unroll
    for (int s = 0; s < S; s++)
        acc += g_outs[(long)l * S * B + (long)s * B + b] * Wfc[s];
    out[i] = acc;
}

// ---------------- host launch ----------------
extern "C" void kernel_launch(void* const* d_in, const int* in_sizes, int n_in,
                              void* d_out, int out_size) {
    const float* x       = (const float*)d_in[0];
    const float* tgt     = (const float*)d_in[1];
    const float* W_ih_e  = (const float*)d_in[2];
    const float* W_hh_e  = (const float*)d_in[3];
    const float* b_ih_e  = (const float*)d_in[4];
    const float* b_hh_e  = (const float*)d_in[5];
    const float* W_ih_d  = (const float*)d_in[6];
    const float* W_hh_d  = (const float*)d_in[7];
    const float* b_ih_d  = (const float*)d_in[8];
    const float* b_hh_d  = (const float*)d_in[9];
    const float* W_in    = (const float*)d_in[10];
    const float* b_in    = (const float*)d_in[11];
    const float* W_out   = (const float*)d_in[12];
    const float* b_out   = (const float*)d_in[13];
    const float* W_fcout = (const float*)d_in[14];
    const float* b_fcout = (const float*)d_in[15];
    const float* W_fc    = (const float*)d_in[16];
    const float* b_fc    = (const float*)d_in[17];
    float* out = (float*)d_out;

    float *Gin, *enc, *k2, *hA, *hB, *inp, *M1, *k2b;
    cudaGetSymbolAddress((void**)&Gin, g_Gin);
    cudaGetSymbolAddress((void**)&enc, g_enc);
    cudaGetSymbolAddress((void**)&k2,  g_k2);
    cudaGetSymbolAddress((void**)&hA,  g_hA);
    cudaGetSymbolAddress((void**)&hB,  g_hB);
    cudaGetSymbolAddress((void**)&inp, g_inp);
    cudaGetSymbolAddress((void**)&M1,  g_M1);
    cudaGetSymbolAddress((void**)&k2b, g_k2b);

    prep_kernel<<<(S * B * H + 255) / 256, 256>>>(x, tgt);
    pc_a<<<(S * H + 255) / 256, 256>>>(W_out, W_fcout, W_in, b_in);
    pc_b<<<(S * H + 255) / 256, 256>>>(W_in, b_in, W_fcout, b_fcout, b_out);
    pc_m1<<<dim3(16, 16, 8), dim3(16, 16)>>>(W_in);

    // 1) encoder input projections (tensor cores): Gin[z=s*12+t][b][g]
    gemm_tc<<<dim3(G / 128, B / 128, 96), 256>>>(
        x, (long)F, 96 * F,
        W_ih_e, (long)G * F, F,
        b_ih_e, b_hh_e, G,
        Gin, (long)B * G, G, F, 12);

    // 2) encoder recurrence (fused tf32 gates + LSTM)
    float* hin = hA; float* hout = hB;
    for (int tt = 0; tt < T; tt++) {
        gates_lstm_tc<<<dim3(H / 16, B / 128, S), 128>>>(
            hin, hout, W_hh_e,
            nullptr, nullptr,
            Gin + (long)tt * B * G, 12l * B * G,
            nullptr, nullptr,
            enc + (long)tt * S * B * H);
        float* tmp = hin; hin = hout; hout = tmp;
    }

    // 3) per-key scalars + transformed keys (tensor cores)
    pc_scal_kernel<<<(T * S * B * 32 + 255) / 256, 256>>>();
    gemm_tc<<<dim3(H / 128, B / 128, T * S), 256>>>(
        enc, (long)B * H, H,
        M1, (long)H * H, H,
        k2b, nullptr, H,
        k2, (long)B * H, H, H, 1);

    // 4) decoder: 48 steps x 2 kernels
    for (int l = 0; l < L; l++) {
        gates_lstm_tc<<<dim3(H / 16, B / 128, S), 128>>>(
            hin, hout, W_hh_d,
            b_ih_d, b_hh_d,
            nullptr, 0,
            inp + (long)l * B, W_ih_d,
            nullptr);
        float* tmp = hin; hin = hout; hout = tmp;
        dec_attn_kernel<<<(S * B * 32 + 255) / 256, 256>>>(hin, W_fcout, l);
    }

    // 5) final mix
    final_kernel<<<(B * L + 255) / 256, 256>>>(W_fc, b_fc, out);
}